// round 12
// baseline (speedup 1.0000x reference)
#include <cuda_runtime.h>
#include <cuda_bf16.h>

#define N_NODES   10000
#define N_EDGES   160000
#define E_TOT     170000        // edges + self loops
#define IN_DIM    128
#define HID       16
#define HEADS     50
#define HH        800           // HEADS*HID
#define HH2       400           // HH/2 (bf16x2 words per node)
#define OUT_DIM   10
#define N_GRAPHS  8
#define NEG_SLOPE 0.2f

// ---------------- scratch (static device globals; no allocation) -------------
__device__ __nv_bfloat162 g_xph[(size_t)N_NODES * HH2]; // projected feats, bf16x2 (16MB)
__device__ float g_as[N_NODES * HEADS];     // alpha_src per node/head
__device__ float g_ad[N_NODES * HEADS];     // alpha_dst per node/head
__device__ float g_gsum[N_GRAPHS * HID];
__device__ float g_cnt[N_GRAPHS];

__device__ int g_src[E_TOT];
__device__ int g_dst[E_TOT];
__device__ int g_batch[N_NODES];
__device__ int g_deg[N_NODES];
__device__ int g_off[N_NODES];              // CSR begin per node (unordered ranges)
__device__ int g_pos[N_NODES];
__device__ int g_csr_src[E_TOT];
__device__ int g_cursor;
__device__ int g_is64_ei;
__device__ int g_is64_b;

// ---------------- K-1: detect index dtype (int32 vs int64 storage) ----------
__global__ void detect_kernel(const int* __restrict__ ei32,
                              const int* __restrict__ b32) {
    if (threadIdx.x == 0) {
        int all0 = 1;
        for (int k = 0; k < 64; k++) {
            int e = (k * 2499 + 7) % N_EDGES;
            if (ei32[2 * e + 1] != 0) { all0 = 0; break; }
        }
        g_is64_ei = all0;
        all0 = 1;
        for (int k = 0; k < 64; k++) {
            int j = 5001 + 2 * k;
            if (b32[j] != 0) { all0 = 0; break; }
        }
        g_is64_b = all0;
    }
}

// ---------------- K0: zero counters / accumulators ----------------
__global__ void init_kernel() {
    int i = blockIdx.x * blockDim.x + threadIdx.x;
    if (i < N_NODES) { g_deg[i] = 0; g_pos[i] = 0; }
    if (i < N_GRAPHS * HID) g_gsum[i] = 0.f;
    if (i < N_GRAPHS)       g_cnt[i] = 0.f;
    if (i == 0)             g_cursor = 0;
}

// ---------------- K0a: canonicalize indices, self loops, count degrees -------
__global__ void build_idx_kernel(const void* __restrict__ ei,
                                 const void* __restrict__ batch) {
    int e = blockIdx.x * blockDim.x + threadIdx.x;
    if (e < E_TOT) {
        int s, d;
        if (e < N_EDGES) {
            if (g_is64_ei) {
                const long long* p = (const long long*)ei;
                s = (int)p[e]; d = (int)p[N_EDGES + e];
            } else {
                const int* p = (const int*)ei;
                s = p[e]; d = p[N_EDGES + e];
            }
            s = min(max(s, 0), N_NODES - 1);
            d = min(max(d, 0), N_NODES - 1);
        } else {
            s = d = e - N_EDGES;
        }
        g_src[e] = s;
        g_dst[e] = d;
        atomicAdd(&g_deg[d], 1);
    }
    if (e < N_NODES) {
        int b = g_is64_b ? (int)((const long long*)batch)[e]
                         : ((const int*)batch)[e];
        g_batch[e] = min(max(b, 0), N_GRAPHS - 1);
    }
}

// ---------------- K0b: unordered CSR range reservation ----------------------
// Block-local scan of 256 degrees + ONE atomic range reservation per block.
// CSR ranges need not be in node order — agg reads [off[n], off[n]+deg[n]).
__global__ void offsets_kernel() {
    __shared__ int sm[256];
    __shared__ int base_sh;
    int i = blockIdx.x * 256 + threadIdx.x;
    int v = (i < N_NODES) ? g_deg[i] : 0;
    sm[threadIdx.x] = v;
    __syncthreads();
    for (int off = 1; off < 256; off <<= 1) {
        int t = (threadIdx.x >= off) ? sm[threadIdx.x - off] : 0;
        __syncthreads();
        sm[threadIdx.x] += t;
        __syncthreads();
    }
    int incl = sm[threadIdx.x];
    if (threadIdx.x == 255) base_sh = atomicAdd(&g_cursor, incl);
    __syncthreads();
    if (i < N_NODES) g_off[i] = base_sh + incl - v;
}

// ---------------- K0c: scatter edges into CSR ----------------
__global__ void scatter_kernel() {
    int e = blockIdx.x * blockDim.x + threadIdx.x;
    if (e >= E_TOT) return;
    int d = g_dst[e];
    int p = atomicAdd(&g_pos[d], 1);
    g_csr_src[g_off[d] + p] = g_src[e];
}

// ---------------- K1: xp = x @ W  (fp32 compute, bf16x2 output) --------------
// 128x128 tile, 256 threads, 8x8 per-thread microtile, K tiled by 16.
__global__ __launch_bounds__(256) void gemm_xp(const float* __restrict__ X,
                                               const float* __restrict__ W) {
    __shared__ float As[16][128];
    __shared__ float Bs[16][128];

    const int tid = threadIdx.x;
    const int tx = tid & 15;
    const int ty = tid >> 4;
    const int rowBase = blockIdx.y * 128;
    const int colBase = blockIdx.x * 128;

    float acc[8][8];
#pragma unroll
    for (int i = 0; i < 8; i++)
#pragma unroll
        for (int j = 0; j < 8; j++) acc[i][j] = 0.f;

    for (int kk = 0; kk < IN_DIM; kk += 16) {
#pragma unroll
        for (int i = 0; i < 2; i++) {
            int s = tid * 2 + i;
            int r = s >> 2;
            int kq = (s & 3) * 4;
            int grow = rowBase + r;
            float4 v = make_float4(0.f, 0.f, 0.f, 0.f);
            if (grow < N_NODES)
                v = *(const float4*)&X[grow * IN_DIM + kk + kq];
            As[kq + 0][r] = v.x; As[kq + 1][r] = v.y;
            As[kq + 2][r] = v.z; As[kq + 3][r] = v.w;
        }
#pragma unroll
        for (int i = 0; i < 2; i++) {
            int s = tid * 2 + i;
            int r = s >> 5;
            int cq = (s & 31) * 4;
            int gcol = colBase + cq;
            float4 v = make_float4(0.f, 0.f, 0.f, 0.f);
            if (gcol < HH)
                v = *(const float4*)&W[(kk + r) * HH + gcol];
            *(float4*)&Bs[r][cq] = v;
        }
        __syncthreads();

#pragma unroll
        for (int k = 0; k < 16; k++) {
            float a[8], b[8];
            *(float4*)&a[0] = *(const float4*)&As[k][ty * 8];
            *(float4*)&a[4] = *(const float4*)&As[k][ty * 8 + 4];
            *(float4*)&b[0] = *(const float4*)&Bs[k][tx * 8];
            *(float4*)&b[4] = *(const float4*)&Bs[k][tx * 8 + 4];
#pragma unroll
            for (int i = 0; i < 8; i++)
#pragma unroll
                for (int j = 0; j < 8; j++)
                    acc[i][j] += a[i] * b[j];
        }
        __syncthreads();
    }

#pragma unroll
    for (int i = 0; i < 8; i++) {
        int gr = rowBase + ty * 8 + i;
        if (gr >= N_NODES) continue;
        int gc = colBase + tx * 8;       // multiple of 8; full 8-col group in range iff gc < HH
        if (gc >= HH) continue;
        __nv_bfloat162 p[4];
#pragma unroll
        for (int j = 0; j < 4; j++)
            p[j] = __floats2bfloat162_rn(acc[i][2 * j], acc[i][2 * j + 1]);
        *(uint4*)&g_xph[(size_t)gr * HH2 + (gc >> 1)] = *(uint4*)p;
    }
}

// ---------------- K2: per-node attention coefficients (bf16 xp) --------------
__global__ void alpha_kernel(const float* __restrict__ a_src,
                             const float* __restrict__ a_dst) {
    int idx = blockIdx.x * blockDim.x + threadIdx.x;
    if (idx >= N_NODES * HEADS) return;
    int n = idx / HEADS;
    int h = idx - n * HEADS;
    const __nv_bfloat162* xp = &g_xph[(size_t)n * HH2 + h * 8];
    const float* as = &a_src[h * HID];
    const float* ad = &a_dst[h * HID];
    float s = 0.f, d = 0.f;
#pragma unroll
    for (int c2 = 0; c2 < 8; c2++) {
        float2 f = __bfloat1622float2(xp[c2]);
        s += f.x * __ldg(&as[2 * c2]) + f.y * __ldg(&as[2 * c2 + 1]);
        d += f.x * __ldg(&ad[2 * c2]) + f.y * __ldg(&ad[2 * c2 + 1]);
    }
    g_as[idx] = s;
    g_ad[idx] = d;
}

// ---------------- K4: SINGLE-PASS softmax + aggregate + pool -----------------
// One warp per dst node. Accumulate unnormalized numerators (lane owns 2 c's x
// 12-13 heads => 26 fp32 regs) AND denominators in one sweep; divide in the
// epilogue; add straight into graph pooling sums.
__global__ __launch_bounds__(256) void agg_csr() {
    __shared__ float ws[8][2][64];    // per-warp double-buffered exp weights
    __shared__ float inv[8][64];      // per-warp inverse denominators
    const int warp = threadIdx.x >> 5;
    const int lane = threadIdx.x & 31;
    const int n = blockIdx.x * 8 + warp;
    if (n >= N_NODES) return;

    const int beg = g_off[n];
    const int deg = g_deg[n];
    const int end = beg + deg;

    const float ad0 = g_ad[n * HEADS + lane];
    const float ad1 = (lane < HEADS - 32) ? g_ad[n * HEADS + 32 + lane] : 0.f;

    const int q  = lane >> 3;                   // head quarter 0..3
    const int c2 = lane & 7;                    // bf16x2 column pair
    const int hbeg = q * 13 - (q == 3 ? 1 : 0); // 0,13,26,38
    const int cnt  = (q < 2) ? 13 : 12;

    float2 acc[13];
#pragma unroll
    for (int k = 0; k < 13; k++) acc[k] = make_float2(0.f, 0.f);
    float d0 = 0.f, d1 = 0.f;

    int src = (deg > 0) ? g_csr_src[beg] : 0;
    for (int e = beg; e < end; e++) {
        int nsrc = (e + 1 < end) ? g_csr_src[e + 1] : 0;
        const int par = (e - beg) & 1;
        const float* as = &g_as[src * HEADS];
        float l0 = as[lane] + ad0;
        l0 = (l0 > 0.f) ? l0 : NEG_SLOPE * l0;
        float e0 = __expf(l0);
        d0 += e0;
        ws[warp][par][lane] = e0;
        if (lane < HEADS - 32) {
            float l1 = as[32 + lane] + ad1;
            l1 = (l1 > 0.f) ? l1 : NEG_SLOPE * l1;
            float e1 = __expf(l1);
            d1 += e1;
            ws[warp][par][32 + lane] = e1;
        }
        __syncwarp();
        const __nv_bfloat162* xp = &g_xph[(size_t)src * HH2 + c2];
#pragma unroll
        for (int k = 0; k < 13; k++) {
            if (k < cnt) {
                float w = ws[warp][par][hbeg + k];
                float2 f = __bfloat1622float2(xp[(hbeg + k) * 8]);
                acc[k].x += w * f.x;
                acc[k].y += w * f.y;
            }
        }
        src = nsrc;
    }

    inv[warp][lane] = 1.f / d0;
    if (lane < HEADS - 32) inv[warp][32 + lane] = 1.f / d1;
    __syncwarp();

    float sx = 0.f, sy = 0.f;
#pragma unroll
    for (int k = 0; k < 13; k++) {
        if (k < cnt) {
            float iv = inv[warp][hbeg + k];
            sx += acc[k].x * iv;
            sy += acc[k].y * iv;
        }
    }
    sx += __shfl_down_sync(0xffffffffu, sx, 16);
    sy += __shfl_down_sync(0xffffffffu, sy, 16);
    sx += __shfl_down_sync(0xffffffffu, sx, 8);
    sy += __shfl_down_sync(0xffffffffu, sy, 8);
    if (lane < 8) {
        int b = g_batch[n];
        atomicAdd(&g_gsum[b * HID + 2 * lane],     sx * (1.f / HEADS));
        atomicAdd(&g_gsum[b * HID + 2 * lane + 1], sy * (1.f / HEADS));
        if (lane == 0) atomicAdd(&g_cnt[b], 1.f);
    }
}

// ---------------- K6: pooled / cnt + bias, then FC ----------------
__global__ void final_kernel(const float* __restrict__ bias,
                             const float* __restrict__ fcw,
                             const float* __restrict__ fcb,
                             float* __restrict__ out) {
    int t = threadIdx.x;
    if (t >= N_GRAPHS * OUT_DIM) return;
    int g = t / OUT_DIM;
    int o = t - g * OUT_DIM;
    float cnt = fmaxf(g_cnt[g], 1.f);
    float acc = fcb[o];
#pragma unroll
    for (int c = 0; c < HID; c++)
        acc += (g_gsum[g * HID + c] / cnt + bias[c]) * fcw[c * OUT_DIM + o];
    out[t] = acc;
}

// ---------------- launch ----------------
extern "C" void kernel_launch(void* const* d_in, const int* in_sizes, int n_in,
                              void* d_out, int out_size) {
    const float* x = 0;  const void* ei = 0;  const void* batch = 0;
    const float* W = 0;  const float* a_src = 0; const float* a_dst = 0;
    const float* bias = 0; const float* fcw = 0; const float* fcb = 0;

    for (int pass = 0; pass < 2 && !x; pass++) {
        a_src = 0; a_dst = 0;
        for (int i = 0; i < n_in; i++) {
            long long sz = in_sizes[i];
            if (pass == 1) {
                if (sz == 2LL * N_EDGES * 8) sz = 2 * N_EDGES;
                else if (sz == (long long)N_NODES * 8) sz = N_NODES;
                else sz /= 4;
            }
            const void* p = d_in[i];
            switch (sz) {
                case (long long)N_NODES * IN_DIM: x = (const float*)p; break;
                case 2LL * N_EDGES:       ei = p; break;
                case (long long)N_NODES:  batch = p; break;
                case (long long)IN_DIM * HH: W = (const float*)p; break;
                case (long long)HEADS * HID:
                    if (!a_src) a_src = (const float*)p; else a_dst = (const float*)p;
                    break;
                case HID:             bias = (const float*)p; break;
                case HID * OUT_DIM:   fcw = (const float*)p; break;
                case OUT_DIM:         fcb = (const float*)p; break;
                default: break;
            }
        }
    }
    float* out = (float*)d_out;

    detect_kernel<<<1, 32>>>((const int*)ei, (const int*)batch);
    init_kernel<<<(N_NODES + 255) / 256, 256>>>();
    build_idx_kernel<<<(E_TOT + 255) / 256, 256>>>(ei, batch);
    offsets_kernel<<<(N_NODES + 255) / 256, 256>>>();
    scatter_kernel<<<(E_TOT + 255) / 256, 256>>>();
    {
        dim3 grid((HH + 127) / 128, (N_NODES + 127) / 128);
        gemm_xp<<<grid, 256>>>(x, W);
    }
    {
        int n = N_NODES * HEADS;
        alpha_kernel<<<(n + 255) / 256, 256>>>(a_src, a_dst);
    }
    agg_csr<<<(N_NODES + 7) / 8, 256>>>();
    final_kernel<<<1, 128>>>(bias, fcw, fcb, out);
}